// round 14
// baseline (speedup 1.0000x reference)
#include <cuda_runtime.h>
#include <math.h>
#include <stdint.h>

#define BB   16
#define CIN  256
#define CC   512
#define LL   4096
#define DD   512
#define UMAX 512
#define BANDCAP 1024
#define BANDHW  0.10f

// -------- scratch (device globals; allocation-free) --------
__device__ float    g_q[(size_t)BB*LL*DD];
__device__ float    g_k[(size_t)BB*LL*DD];
__device__ float    g_v[(size_t)BB*LL*DD];
__device__ float    g_ksamp[(size_t)BB*UMAX*DD];
__device__ unsigned g_Mmax[(size_t)BB*LL];
__device__ float    g_Msum[(size_t)BB*LL];
__device__ int      g_mtop[(size_t)BB*UMAX];
__device__ int      g_band[(size_t)BB*BANDCAP];
__device__ float    g_Mexact[(size_t)BB*BANDCAP];
__device__ int      g_bandinfo[BB*2];           // {sure_in_count a, band_len}
__device__ float    g_qr[(size_t)BB*UMAX*DD];
__device__ float    g_scores[(size_t)BB*UMAX*LL];
__device__ float    g_vmean[(size_t)BB*DD];
__device__ float    g_upd[(size_t)BB*UMAX*DD];

// -------- tf32 helpers --------
__device__ __forceinline__ float tf32r(float a) {
    uint32_t r;
    asm("cvt.rna.tf32.f32 %0, %1;" : "=r"(r) : "f"(a));
    return __uint_as_float(r);
}
__device__ __forceinline__ void mma_tf32(float c[4],
                                         uint32_t a0, uint32_t a1, uint32_t a2, uint32_t a3,
                                         uint32_t b0, uint32_t b1) {
    asm("mma.sync.aligned.m16n8k8.row.col.f32.tf32.tf32.f32 "
        "{%0,%1,%2,%3},{%4,%5,%6,%7},{%8,%9},{%0,%1,%2,%3};"
        : "+f"(c[0]), "+f"(c[1]), "+f"(c[2]), "+f"(c[3])
        : "r"(a0), "r"(a1), "r"(a2), "r"(a3), "r"(b0), "r"(b1));
}
__device__ __forceinline__ unsigned fkey(float f) {
    unsigned u = __float_as_uint(f);
    return (u & 0x80000000u) ? ~u : (u | 0x80000000u);
}
__device__ __forceinline__ float fdecode(unsigned k) {
    return (k & 0x80000000u) ? __uint_as_float(k ^ 0x80000000u) : __uint_as_float(~k);
}

// ======== generic tiled GEMM (R9-proven), 128x64 block, 8 warps, 32x32 warp tile ========
// C[gm*ldc_m + gn*ldc_n] = alpha * sum_k A * B (+ bias[n]); XA=3: 3xTF32; XA=1: plain.
// FUSEM: per-row max & sum atomically merged into Mmax/Msum instead of C write.
template<bool AKC, bool BKC, bool SPLITA, int XA, bool FUSEM>
__global__ void __launch_bounds__(256)
gemm_tc_kernel(const float* __restrict__ A, const float* __restrict__ A2,
               const float* __restrict__ Bm, float* __restrict__ C,
               int M, int N, int K, int Ksplit,
               long lda_m, long lda_k, long ldb_n, long ldb_k,
               long ldc_m, long ldc_n,
               long sA, long sB, long sC,
               const float* __restrict__ bias, float alpha,
               unsigned* __restrict__ Mmax, float* __restrict__ Msum)
{
    __shared__ float As_hi[16][136];
    __shared__ float As_lo[16][136];
    __shared__ float Bs_hi[16][72];
    __shared__ float Bs_lo[16][72];

    int b = blockIdx.z;
    const float* Ab  = A  + (size_t)b * sA;
    const float* A2b = SPLITA ? (A2 + (size_t)b * sA) : nullptr;
    const float* Bb  = Bm + (size_t)b * sB;
    float*       Cb  = C  + (size_t)b * sC;
    int m0 = blockIdx.y * 128, n0 = blockIdx.x * 64;
    int tid  = threadIdx.x;
    int wid  = tid >> 5, lane = tid & 31;
    int wm = (wid & 3) * 32;
    int wn = (wid >> 2) * 32;
    int lr = lane >> 2, lc = lane & 3;

    float acc[2][4][4];
    #pragma unroll
    for (int i = 0; i < 2; i++)
        #pragma unroll
        for (int j = 0; j < 4; j++)
            #pragma unroll
            for (int t = 0; t < 4; t++) acc[i][j][t] = 0.f;

    float aPre[8], bPre[4];

    auto gload = [&](int k0) {
        #pragma unroll
        for (int i = 0; i < 8; i++) {
            int linear = tid + i * 256;
            int mm, kk;
            if (AKC) { kk = linear & 15;  mm = linear >> 4; }
            else     { mm = linear & 127; kk = linear >> 7; }
            int gm = m0 + mm, gk = k0 + kk;
            float val = 0.f;
            if (gm < M) {
                if (SPLITA) {
                    val = (gk < Ksplit)
                        ? Ab [(size_t)gm * lda_m + (size_t)gk          * lda_k]
                        : A2b[(size_t)gm * lda_m + (size_t)(gk-Ksplit) * lda_k];
                } else {
                    val = Ab[(size_t)gm * lda_m + (size_t)gk * lda_k];
                }
            }
            aPre[i] = val;
        }
        #pragma unroll
        for (int i = 0; i < 4; i++) {
            int linear = tid + i * 256;
            int nn, kk;
            if (BKC) { kk = linear & 15; nn = linear >> 4; }
            else     { nn = linear & 63; kk = linear >> 6; }
            int gn = n0 + nn, gk = k0 + kk;
            float val = 0.f;
            if (gn < N) val = Bb[(size_t)gn * ldb_n + (size_t)gk * ldb_k];
            bPre[i] = val;
        }
    };
    auto stile = [&]() {
        #pragma unroll
        for (int i = 0; i < 8; i++) {
            int linear = tid + i * 256;
            int mm, kk;
            if (AKC) { kk = linear & 15;  mm = linear >> 4; }
            else     { mm = linear & 127; kk = linear >> 7; }
            float v = aPre[i];
            float h = tf32r(v);
            As_hi[kk][mm] = h;
            if (XA == 3) As_lo[kk][mm] = tf32r(v - h);
        }
        #pragma unroll
        for (int i = 0; i < 4; i++) {
            int linear = tid + i * 256;
            int nn, kk;
            if (BKC) { kk = linear & 15; nn = linear >> 4; }
            else     { nn = linear & 63; kk = linear >> 6; }
            float v = bPre[i];
            float h = tf32r(v);
            Bs_hi[kk][nn] = h;
            if (XA == 3) Bs_lo[kk][nn] = tf32r(v - h);
        }
    };

    gload(0);
    for (int k0 = 0; k0 < K; k0 += 16) {
        stile();
        __syncthreads();
        if (k0 + 16 < K) gload(k0 + 16);

        #pragma unroll
        for (int kt = 0; kt < 2; kt++) {
            int kb = kt * 8;
            uint32_t ah[2][4], al[2][4];
            #pragma unroll
            for (int mt = 0; mt < 2; mt++) {
                int mb = wm + mt * 16;
                ah[mt][0] = __float_as_uint(As_hi[kb+lc  ][mb+lr  ]);
                ah[mt][1] = __float_as_uint(As_hi[kb+lc  ][mb+lr+8]);
                ah[mt][2] = __float_as_uint(As_hi[kb+lc+4][mb+lr  ]);
                ah[mt][3] = __float_as_uint(As_hi[kb+lc+4][mb+lr+8]);
                if (XA == 3) {
                    al[mt][0] = __float_as_uint(As_lo[kb+lc  ][mb+lr  ]);
                    al[mt][1] = __float_as_uint(As_lo[kb+lc  ][mb+lr+8]);
                    al[mt][2] = __float_as_uint(As_lo[kb+lc+4][mb+lr  ]);
                    al[mt][3] = __float_as_uint(As_lo[kb+lc+4][mb+lr+8]);
                }
            }
            #pragma unroll
            for (int nt = 0; nt < 4; nt++) {
                int nb = wn + nt * 8;
                uint32_t b0 = __float_as_uint(Bs_hi[kb+lc  ][nb+lr]);
                uint32_t b1 = __float_as_uint(Bs_hi[kb+lc+4][nb+lr]);
                uint32_t l0 = 0, l1 = 0;
                if (XA == 3) {
                    l0 = __float_as_uint(Bs_lo[kb+lc  ][nb+lr]);
                    l1 = __float_as_uint(Bs_lo[kb+lc+4][nb+lr]);
                }
                #pragma unroll
                for (int mt = 0; mt < 2; mt++) {
                    if (XA == 3) {
                        mma_tf32(acc[mt][nt], ah[mt][0], ah[mt][1], ah[mt][2], ah[mt][3], l0, l1);
                        mma_tf32(acc[mt][nt], al[mt][0], al[mt][1], al[mt][2], al[mt][3], b0, b1);
                    }
                    mma_tf32(acc[mt][nt], ah[mt][0], ah[mt][1], ah[mt][2], ah[mt][3], b0, b1);
                }
            }
        }
        __syncthreads();
    }

    if (FUSEM) {
        unsigned* Mx = Mmax + (size_t)b * LL;
        float*    Ms = Msum + (size_t)b * LL;
        #pragma unroll
        for (int mt = 0; mt < 2; mt++) {
            float mx[2] = {-INFINITY, -INFINITY};
            float sm[2] = {0.f, 0.f};
            #pragma unroll
            for (int nt = 0; nt < 4; nt++) {
                int gc0 = n0 + wn + nt*8 + 2*lc;
                #pragma unroll
                for (int t = 0; t < 4; t++) {
                    int gn = gc0 + (t & 1);
                    int h = t >> 1;
                    if (gn < N) {
                        float v = acc[mt][nt][t];
                        mx[h] = fmaxf(mx[h], v);
                        sm[h] += v;
                    }
                }
            }
            #pragma unroll
            for (int o = 1; o <= 2; o <<= 1) {
                #pragma unroll
                for (int h = 0; h < 2; h++) {
                    mx[h] = fmaxf(mx[h], __shfl_xor_sync(0xFFFFFFFFu, mx[h], o));
                    sm[h] += __shfl_xor_sync(0xFFFFFFFFu, sm[h], o);
                }
            }
            if (lc == 0) {
                #pragma unroll
                for (int h = 0; h < 2; h++) {
                    int gm = m0 + wm + mt*16 + lr + h*8;
                    if (gm < M) {
                        atomicMax(&Mx[gm], fkey(mx[h]));
                        atomicAdd(&Ms[gm], sm[h]);
                    }
                }
            }
        }
    } else {
        #pragma unroll
        for (int mt = 0; mt < 2; mt++) {
            #pragma unroll
            for (int nt = 0; nt < 4; nt++) {
                int gr0 = m0 + wm + mt*16 + lr;
                int gc0 = n0 + wn + nt*8 + 2*lc;
                #pragma unroll
                for (int t = 0; t < 4; t++) {
                    int gm = gr0 + ((t >= 2) ? 8 : 0);
                    int gn = gc0 + (t & 1);
                    if (gm >= M || gn >= N) continue;
                    float v = acc[mt][nt][t] * alpha;
                    if (bias) v += bias[gn];
                    Cb[(size_t)gm * ldc_m + (size_t)gn * ldc_n] = v;
                }
            }
        }
    }
}

// ======== fused q+k projection: shares A (x) tiles/frags across two B operands ========
// M=LL (spatial s), N=DD (channel o), K=CC split at CIN. Both outputs 3xTF32,
// stored transposed (flat channel-major == the reference's reshaped (L,D) view).
__global__ void __launch_bounds__(256)
projqk_kernel(const float* __restrict__ in1, const float* __restrict__ in2,
              const float* __restrict__ Wq, const float* __restrict__ Wk,
              const float* __restrict__ bq, const float* __restrict__ bk,
              float* __restrict__ qo, float* __restrict__ ko)
{
    __shared__ float As_hi[16][136];
    __shared__ float As_lo[16][136];
    __shared__ float BsQ_hi[16][72];
    __shared__ float BsQ_lo[16][72];
    __shared__ float BsK_hi[16][72];
    __shared__ float BsK_lo[16][72];

    int b = blockIdx.z;
    const float* A1 = in1 + (size_t)b * CIN * LL;
    const float* A2 = in2 + (size_t)b * CIN * LL;
    float* qb = qo + (size_t)b * LL * DD;
    float* kb = ko + (size_t)b * LL * DD;
    int m0 = blockIdx.y * 128, n0 = blockIdx.x * 64;
    int tid = threadIdx.x, wid = tid >> 5, lane = tid & 31;
    int wm = (wid & 3) * 32, wn = (wid >> 2) * 32;
    int lr = lane >> 2, lc = lane & 3;

    float accQ[2][4][4], accK[2][4][4];
    #pragma unroll
    for (int i = 0; i < 2; i++)
        #pragma unroll
        for (int j = 0; j < 4; j++)
            #pragma unroll
            for (int t = 0; t < 4; t++) { accQ[i][j][t] = 0.f; accK[i][j][t] = 0.f; }

    float aPre[8], bPreQ[4], bPreK[4];

    auto gload = [&](int k0) {
        #pragma unroll
        for (int i = 0; i < 8; i++) {
            int linear = tid + i * 256;
            int mm = linear & 127, kk = linear >> 7;
            int gm = m0 + mm, gk = k0 + kk;
            aPre[i] = (gk < CIN) ? A1[(size_t)gm + (size_t)gk * LL]
                                 : A2[(size_t)gm + (size_t)(gk - CIN) * LL];
        }
        #pragma unroll
        for (int i = 0; i < 4; i++) {
            int linear = tid + i * 256;
            int kk = linear & 15, nn = linear >> 4;
            int gn = n0 + nn, gk = k0 + kk;
            bPreQ[i] = Wq[(size_t)gn * CC + gk];
            bPreK[i] = Wk[(size_t)gn * CC + gk];
        }
    };
    auto stile = [&]() {
        #pragma unroll
        for (int i = 0; i < 8; i++) {
            int linear = tid + i * 256;
            int mm = linear & 127, kk = linear >> 7;
            float v = aPre[i], h = tf32r(v);
            As_hi[kk][mm] = h;
            As_lo[kk][mm] = tf32r(v - h);
        }
        #pragma unroll
        for (int i = 0; i < 4; i++) {
            int linear = tid + i * 256;
            int kk = linear & 15, nn = linear >> 4;
            float v = bPreQ[i], h = tf32r(v);
            BsQ_hi[kk][nn] = h;
            BsQ_lo[kk][nn] = tf32r(v - h);
            v = bPreK[i]; h = tf32r(v);
            BsK_hi[kk][nn] = h;
            BsK_lo[kk][nn] = tf32r(v - h);
        }
    };

    gload(0);
    for (int k0 = 0; k0 < CC; k0 += 16) {
        stile();
        __syncthreads();
        if (k0 + 16 < CC) gload(k0 + 16);

        #pragma unroll
        for (int kt = 0; kt < 2; kt++) {
            int kb2 = kt * 8;
            uint32_t ah[2][4], al[2][4];
            #pragma unroll
            for (int mt = 0; mt < 2; mt++) {
                int mb = wm + mt * 16;
                ah[mt][0] = __float_as_uint(As_hi[kb2+lc  ][mb+lr  ]);
                ah[mt][1] = __float_as_uint(As_hi[kb2+lc  ][mb+lr+8]);
                ah[mt][2] = __float_as_uint(As_hi[kb2+lc+4][mb+lr  ]);
                ah[mt][3] = __float_as_uint(As_hi[kb2+lc+4][mb+lr+8]);
                al[mt][0] = __float_as_uint(As_lo[kb2+lc  ][mb+lr  ]);
                al[mt][1] = __float_as_uint(As_lo[kb2+lc  ][mb+lr+8]);
                al[mt][2] = __float_as_uint(As_lo[kb2+lc+4][mb+lr  ]);
                al[mt][3] = __float_as_uint(As_lo[kb2+lc+4][mb+lr+8]);
            }
            #pragma unroll
            for (int nt = 0; nt < 4; nt++) {
                int nb = wn + nt * 8;
                {
                    uint32_t b0 = __float_as_uint(BsQ_hi[kb2+lc  ][nb+lr]);
                    uint32_t b1 = __float_as_uint(BsQ_hi[kb2+lc+4][nb+lr]);
                    uint32_t l0 = __float_as_uint(BsQ_lo[kb2+lc  ][nb+lr]);
                    uint32_t l1 = __float_as_uint(BsQ_lo[kb2+lc+4][nb+lr]);
                    #pragma unroll
                    for (int mt = 0; mt < 2; mt++) {
                        mma_tf32(accQ[mt][nt], ah[mt][0], ah[mt][1], ah[mt][2], ah[mt][3], l0, l1);
                        mma_tf32(accQ[mt][nt], al[mt][0], al[mt][1], al[mt][2], al[mt][3], b0, b1);
                        mma_tf32(accQ[mt][nt], ah[mt][0], ah[mt][1], ah[mt][2], ah[mt][3], b0, b1);
                    }
                }
                {
                    uint32_t b0 = __float_as_uint(BsK_hi[kb2+lc  ][nb+lr]);
                    uint32_t b1 = __float_as_uint(BsK_hi[kb2+lc+4][nb+lr]);
                    uint32_t l0 = __float_as_uint(BsK_lo[kb2+lc  ][nb+lr]);
                    uint32_t l1 = __float_as_uint(BsK_lo[kb2+lc+4][nb+lr]);
                    #pragma unroll
                    for (int mt = 0; mt < 2; mt++) {
                        mma_tf32(accK[mt][nt], ah[mt][0], ah[mt][1], ah[mt][2], ah[mt][3], l0, l1);
                        mma_tf32(accK[mt][nt], al[mt][0], al[mt][1], al[mt][2], al[mt][3], b0, b1);
                        mma_tf32(accK[mt][nt], ah[mt][0], ah[mt][1], ah[mt][2], ah[mt][3], b0, b1);
                    }
                }
            }
        }
        __syncthreads();
    }

    // transposed store: C[gm + gn*LL] (flat channel-major)
    #pragma unroll
    for (int mt = 0; mt < 2; mt++) {
        #pragma unroll
        for (int nt = 0; nt < 4; nt++) {
            int gr0 = m0 + wm + mt*16 + lr;
            int gc0 = n0 + wn + nt*8 + 2*lc;
            #pragma unroll
            for (int t = 0; t < 4; t++) {
                int gm = gr0 + ((t >= 2) ? 8 : 0);
                int gn = gc0 + (t & 1);
                qb[(size_t)gm + (size_t)gn * LL] = accQ[mt][nt][t] + bq[gn];
                kb[(size_t)gm + (size_t)gn * LL] = accK[mt][nt][t] + bk[gn];
            }
        }
    }
}

// -------- init fused M buffers --------
__global__ void minit_kernel() {
    int i = blockIdx.x * blockDim.x + threadIdx.x;
    if (i < BB * LL) { g_Mmax[i] = fkey(-INFINITY); g_Msum[i] = 0.f; }
}

// -------- gather sampled K rows --------
__global__ void gather_ksample_kernel(const int* __restrict__ idx, int U) {
    size_t t = (size_t)blockIdx.x * blockDim.x + threadIdx.x;
    size_t total = (size_t)BB * U * DD;
    if (t >= total) return;
    int d = (int)(t % DD);
    size_t rest = t / DD;
    int s = (int)(rest % U);
    int b = (int)(rest / U);
    g_ksamp[((size_t)b * U + s) * DD + d] = g_k[((size_t)b * LL + idx[s]) * DD + d];
}

// -------- top-k on cheap M + band extraction --------
__global__ void topk_band_kernel(int u) {
    __shared__ float sv[LL];
    __shared__ int   si[LL];
    __shared__ int sA, sB;
    int b = blockIdx.x;
    for (int i = threadIdx.x; i < LL; i += blockDim.x) {
        sv[i] = fdecode(g_Mmax[(size_t)b*LL + i]) - g_Msum[(size_t)b*LL + i] * (1.0f/(float)LL);
        si[i] = i;
    }
    __syncthreads();
    for (int k = 2; k <= LL; k <<= 1) {
        for (int j = k >> 1; j > 0; j >>= 1) {
            for (int t = threadIdx.x; t < LL; t += blockDim.x) {
                int ixj = t ^ j;
                if (ixj > t) {
                    bool dirDesc = ((t & k) == 0);
                    float va = sv[t], vb = sv[ixj];
                    int   ia = si[t], ib = si[ixj];
                    bool aBeforeB = (va > vb) || (va == vb && ia < ib);
                    bool swp = dirDesc ? !aBeforeB : aBeforeB;
                    if (swp) { sv[t] = vb; sv[ixj] = va; si[t] = ib; si[ixj] = ia; }
                }
            }
            __syncthreads();
        }
    }
    float theta = sv[u-1];
    float hiv = theta + BANDHW, lov = theta - BANDHW;
    if (threadIdx.x == 0) { sA = 0; sB = LL; }
    __syncthreads();
    for (int i = threadIdx.x; i < LL; i += blockDim.x) {
        if (sv[i] <= hiv && (i == 0 || sv[i-1] > hiv)) sA = i;
        if (sv[i] <  lov && (i == 0 || sv[i-1] >= lov)) sB = i;
    }
    __syncthreads();
    int a = sA;
    int len = sB - a; if (len > BANDCAP) len = BANDCAP;
    for (int i = threadIdx.x; i < u; i += blockDim.x) g_mtop[(size_t)b*u + i] = si[i];
    for (int j = threadIdx.x; j < len; j += blockDim.x) g_band[(size_t)b*BANDCAP + j] = si[a + j];
    if (threadIdx.x == 0) { g_bandinfo[b*2] = a; g_bandinfo[b*2+1] = len; }
}

// -------- exact M recompute for band rows (fp32 FFMA from stored q/ksamp) --------
__global__ void refine_kernel(int U) {
    __shared__ float qrow[DD];
    __shared__ float wmx[8], wsm[8];
    int b = blockIdx.y, pos = blockIdx.x;
    int len = g_bandinfo[b*2+1];
    if (pos >= len) return;
    int l = g_band[(size_t)b*BANDCAP + pos];
    const float* qp = g_q + ((size_t)b*LL + l)*DD;
    for (int d = threadIdx.x; d < DD; d += 256) qrow[d] = qp[d];
    __syncthreads();
    int wid = threadIdx.x >> 5, lane = threadIdx.x & 31;
    float mx = -INFINITY, sm = 0.f;
    for (int s = wid; s < U; s += 8) {
        const float* kr = g_ksamp + ((size_t)b*U + s)*DD;
        float p = 0.f;
        #pragma unroll 4
        for (int d = lane; d < DD; d += 32) p += qrow[d] * kr[d];
        #pragma unroll
        for (int o = 16; o; o >>= 1) p += __shfl_xor_sync(0xFFFFFFFFu, p, o);
        mx = fmaxf(mx, p);
        sm += p;
    }
    if (lane == 0) { wmx[wid] = mx; wsm[wid] = sm; }
    __syncthreads();
    if (threadIdx.x == 0) {
        float M = -INFINITY, S = 0.f;
        #pragma unroll
        for (int w = 0; w < 8; w++) { M = fmaxf(M, wmx[w]); S += wsm[w]; }
        g_Mexact[(size_t)b*BANDCAP + pos] = M - S * (1.0f/(float)LL);
    }
}

// -------- final selection: sure-in + best (u-a) of band by exact M --------
__global__ void select_kernel(int u) {
    __shared__ float sv[BANDCAP];
    __shared__ int   si[BANDCAP];
    int b = blockIdx.x;
    int a = g_bandinfo[b*2], len = g_bandinfo[b*2+1];
    for (int i = threadIdx.x; i < BANDCAP; i += blockDim.x) {
        if (i < len) { sv[i] = g_Mexact[(size_t)b*BANDCAP + i]; si[i] = g_band[(size_t)b*BANDCAP + i]; }
        else         { sv[i] = -INFINITY; si[i] = 0x7fffffff; }
    }
    __syncthreads();
    for (int k = 2; k <= BANDCAP; k <<= 1) {
        for (int j = k >> 1; j > 0; j >>= 1) {
            for (int t = threadIdx.x; t < BANDCAP; t += blockDim.x) {
                int ixj = t ^ j;
                if (ixj > t) {
                    bool dirDesc = ((t & k) == 0);
                    float va = sv[t], vb = sv[ixj];
                    int   ia = si[t], ib = si[ixj];
                    bool aBeforeB = (va > vb) || (va == vb && ia < ib);
                    bool swp = dirDesc ? !aBeforeB : aBeforeB;
                    if (swp) { sv[t] = vb; sv[ixj] = va; si[t] = ib; si[ixj] = ia; }
                }
            }
            __syncthreads();
        }
    }
    int need = u - a;
    for (int j = threadIdx.x; j < need; j += blockDim.x)
        g_mtop[(size_t)b*u + a + j] = si[j];
}

// -------- gather Q_reduce rows --------
__global__ void gather_qr_kernel(int u) {
    size_t t = (size_t)blockIdx.x * blockDim.x + threadIdx.x;
    size_t total = (size_t)BB * u * DD;
    if (t >= total) return;
    int d = (int)(t % DD);
    size_t rest = t / DD;
    int uu = (int)(rest % u);
    int b  = (int)(rest / u);
    int l = g_mtop[(size_t)b*u + uu];
    g_qr[((size_t)b*u + uu) * DD + d] = g_q[((size_t)b*LL + l) * DD + d];
}

// -------- row softmax over L --------
__global__ void softmax_kernel() {
    __shared__ float row[LL];
    __shared__ float red[256];
    size_t r = blockIdx.x;
    float* ptr = g_scores + r * (size_t)LL;
    float mx = -INFINITY;
    for (int i = threadIdx.x; i < LL; i += 256) { float x = ptr[i]; row[i] = x; mx = fmaxf(mx, x); }
    red[threadIdx.x] = mx; __syncthreads();
    for (int s = 128; s; s >>= 1) { if (threadIdx.x < s) red[threadIdx.x] = fmaxf(red[threadIdx.x], red[threadIdx.x+s]); __syncthreads(); }
    mx = red[0]; __syncthreads();
    float sm = 0.f;
    for (int i = threadIdx.x; i < LL; i += 256) { float e = __expf(row[i] - mx); row[i] = e; sm += e; }
    red[threadIdx.x] = sm; __syncthreads();
    for (int s = 128; s; s >>= 1) { if (threadIdx.x < s) red[threadIdx.x] += red[threadIdx.x+s]; __syncthreads(); }
    float inv = 1.f / red[0];
    for (int i = threadIdx.x; i < LL; i += 256) ptr[i] = row[i] * inv;
}

// -------- v mean over L --------
__global__ void vmean_zero_kernel() {
    int i = blockIdx.x * blockDim.x + threadIdx.x;
    if (i < BB * DD) g_vmean[i] = 0.f;
}
__global__ void vmean_kernel() {
    int b = blockIdx.x, ch = blockIdx.y;
    int d = threadIdx.x;
    float s = 0.f;
    int l0 = ch * 128;
    for (int l = l0; l < l0 + 128; l++) s += g_v[((size_t)b*LL + l) * DD + d];
    atomicAdd(&g_vmean[b*DD + d], s * (1.0f / (float)LL));
}

// -------- output: broadcast mean then scatter updated rows --------
__global__ void broadcast_out_kernel(float* __restrict__ out) {
    size_t t = (size_t)blockIdx.x * blockDim.x + threadIdx.x;
    if (t >= (size_t)BB*LL*DD) return;
    int d = (int)(t % DD);
    int b = (int)(t / ((size_t)LL*DD));
    out[t] = g_vmean[b*DD + d];
}
__global__ void scatter_out_kernel(float* __restrict__ out, int u) {
    size_t t = (size_t)blockIdx.x * blockDim.x + threadIdx.x;
    size_t total = (size_t)BB * u * DD;
    if (t >= total) return;
    int d = (int)(t % DD);
    size_t rest = t / DD;
    int uu = (int)(rest % u);
    int b  = (int)(rest / u);
    int l = g_mtop[(size_t)b*u + uu];
    out[((size_t)b*LL + l) * DD + d] = g_upd[((size_t)b*u + uu) * DD + d];
}

extern "C" void kernel_launch(void* const* d_in, const int* in_sizes, int n_in,
                              void* d_out, int out_size)
{
    const float* in1 = (const float*)d_in[0];
    const float* in2 = (const float*)d_in[1];
    const float* Wq  = (const float*)d_in[2];
    const float* bq  = (const float*)d_in[3];
    const float* Wk  = (const float*)d_in[4];
    const float* bk  = (const float*)d_in[5];
    const float* Wv  = (const float*)d_in[6];
    const float* bv  = (const float*)d_in[7];
    const int*   idx = (const int*)d_in[8];
    int U = in_sizes[8];
    int u = (U < LL) ? U : LL;
    float* out = (float*)d_out;

    float *q, *k, *v, *ksamp, *qr, *scores, *upd;
    unsigned* mmax; float* msum;
    cudaGetSymbolAddress((void**)&q,      g_q);
    cudaGetSymbolAddress((void**)&k,      g_k);
    cudaGetSymbolAddress((void**)&v,      g_v);
    cudaGetSymbolAddress((void**)&ksamp,  g_ksamp);
    cudaGetSymbolAddress((void**)&qr,     g_qr);
    cudaGetSymbolAddress((void**)&scores, g_scores);
    cudaGetSymbolAddress((void**)&upd,    g_upd);
    cudaGetSymbolAddress((void**)&mmax,   g_Mmax);
    cudaGetSymbolAddress((void**)&msum,   g_Msum);

    dim3 blk(256);
    const float scale = rsqrtf(512.0f);  // 1/sqrt(IN_CHANNELS)

    // 1) fused q+k projection (3xTF32) + v projection (1xTF32)
    {
        dim3 grid(DD/64, LL/128, BB);
        projqk_kernel<<<grid, blk>>>(in1, in2, Wq, Wk, bq, bk, q, k);
        gemm_tc_kernel<false,true,true,1,false><<<grid, blk>>>(in1, in2, Wv, v, LL, DD, CC, CIN,
            1L, (long)LL, (long)CC, 1L, 1L, (long)LL, (long)CIN*LL, 0L, (long)LL*DD, bv, 1.0f, nullptr, nullptr);
    }

    // 2) gather sampled K rows + init M buffers
    {
        size_t total = (size_t)BB * U * DD;
        gather_ksample_kernel<<<(unsigned)((total + 255) / 256), blk>>>(idx, U);
        minit_kernel<<<(BB*LL + 255)/256, blk>>>();
    }

    // 3) cheap QKs fused with M-stats (1xTF32; refined below)
    {
        dim3 grid((U + 63)/64, LL/128, BB);
        gemm_tc_kernel<true,true,false,1,true><<<grid, blk>>>(q, nullptr, ksamp, nullptr, LL, U, DD, 0,
            (long)DD, 1L, (long)DD, 1L, 0L, 0L, (long)LL*DD, (long)U*DD, 0L, nullptr, 1.0f, mmax, msum);
    }

    // 4) top-k on cheap M + band; exact refine of band; final set selection
    topk_band_kernel<<<BB, 1024>>>(u);
    {
        dim3 grid(BANDCAP, BB);
        refine_kernel<<<grid, blk>>>(U);
    }
    select_kernel<<<BB, 1024>>>(u);

    // 5) gather Q_reduce
    {
        size_t total = (size_t)BB * u * DD;
        gather_qr_kernel<<<(unsigned)((total + 255) / 256), blk>>>(u);
    }

    // 6) scores[uu,l] = (Qr[uu,:] . k[l,:]) * scale   (1xTF32)
    {
        dim3 grid(LL/64, (u + 127)/128, BB);
        gemm_tc_kernel<true,true,false,1,false><<<grid, blk>>>(qr, nullptr, k, scores, u, LL, DD, 0,
            (long)DD, 1L, (long)DD, 1L, (long)LL, 1L, (long)u*DD, (long)LL*DD, (long)u*LL, nullptr, scale, nullptr, nullptr);
    }

    // 7) softmax over L (in place)
    softmax_kernel<<<BB*u, blk>>>();

    // 8) upd[uu,d] = sum_l attn[uu,l]*v[l,d]   (1xTF32)
    {
        dim3 grid(DD/64, (u + 127)/128, BB);
        gemm_tc_kernel<true,false,false,1,false><<<grid, blk>>>(scores, nullptr, v, upd, u, DD, LL, 0,
            (long)LL, 1L, 1L, (long)DD, (long)DD, 1L, (long)u*LL, (long)LL*DD, (long)u*DD, nullptr, 1.0f, nullptr, nullptr);
    }

    // 9) v mean, broadcast, scatter
    vmean_zero_kernel<<<(BB*DD + 255)/256, blk>>>();
    {
        dim3 grid(BB, 32);
        vmean_kernel<<<grid, DD>>>();
    }
    {
        size_t total = (size_t)BB * LL * DD;
        broadcast_out_kernel<<<(unsigned)((total + 255)/256), blk>>>(out);
        size_t st = (size_t)BB * u * DD;
        scatter_out_kernel<<<(unsigned)((st + 255)/256), blk>>>(out, u);
    }
}

// round 15
// speedup vs baseline: 1.4407x; 1.4407x over previous
#include <cuda_runtime.h>
#include <math.h>
#include <stdint.h>

#define BB   16
#define CIN  256
#define CC   512
#define LL   4096
#define DD   512
#define UMAX 512
#define BANDCAP 1024
#define BANDHW  0.10f

// -------- scratch (device globals; allocation-free) --------
__device__ float    g_q[(size_t)BB*LL*DD];
__device__ float    g_k[(size_t)BB*LL*DD];
__device__ float    g_v[(size_t)BB*LL*DD];
__device__ float    g_ksamp[(size_t)BB*UMAX*DD];
__device__ unsigned g_Mmax[(size_t)BB*LL];
__device__ float    g_Msum[(size_t)BB*LL];
__device__ int      g_mtop[(size_t)BB*UMAX];
__device__ int      g_band[(size_t)BB*BANDCAP];
__device__ float    g_Mexact[(size_t)BB*BANDCAP];
__device__ int      g_bandinfo[BB*2];           // {sure_in_count a, band_len}
__device__ float    g_qr[(size_t)BB*UMAX*DD];
__device__ float    g_scores[(size_t)BB*UMAX*LL];
__device__ float    g_vmean[(size_t)BB*DD];
__device__ float    g_upd[(size_t)BB*UMAX*DD];

// -------- tf32 helpers --------
__device__ __forceinline__ float tf32r(float a) {
    uint32_t r;
    asm("cvt.rna.tf32.f32 %0, %1;" : "=r"(r) : "f"(a));
    return __uint_as_float(r);
}
__device__ __forceinline__ void mma_tf32(float c[4],
                                         uint32_t a0, uint32_t a1, uint32_t a2, uint32_t a3,
                                         uint32_t b0, uint32_t b1) {
    asm("mma.sync.aligned.m16n8k8.row.col.f32.tf32.tf32.f32 "
        "{%0,%1,%2,%3},{%4,%5,%6,%7},{%8,%9},{%0,%1,%2,%3};"
        : "+f"(c[0]), "+f"(c[1]), "+f"(c[2]), "+f"(c[3])
        : "r"(a0), "r"(a1), "r"(a2), "r"(a3), "r"(b0), "r"(b1));
}
__device__ __forceinline__ unsigned fkey(float f) {
    unsigned u = __float_as_uint(f);
    return (u & 0x80000000u) ? ~u : (u | 0x80000000u);
}
__device__ __forceinline__ float fdecode(unsigned k) {
    return (k & 0x80000000u) ? __uint_as_float(k ^ 0x80000000u) : __uint_as_float(~k);
}

// ======== generic tiled GEMM (R9-proven), 128x64 block, 8 warps, 32x32 warp tile ========
// C[gm*ldc_m + gn*ldc_n] = alpha * sum_k A * B (+ bias[n]); XA=3: 3xTF32; XA=1: plain.
// FUSEM: per-row max & sum atomically merged into Mmax/Msum instead of C write.
template<bool AKC, bool BKC, bool SPLITA, int XA, bool FUSEM>
__global__ void __launch_bounds__(256)
gemm_tc_kernel(const float* __restrict__ A, const float* __restrict__ A2,
               const float* __restrict__ Bm, float* __restrict__ C,
               int M, int N, int K, int Ksplit,
               long lda_m, long lda_k, long ldb_n, long ldb_k,
               long ldc_m, long ldc_n,
               long sA, long sB, long sC,
               const float* __restrict__ bias, float alpha,
               unsigned* __restrict__ Mmax, float* __restrict__ Msum)
{
    __shared__ float As_hi[16][136];
    __shared__ float As_lo[16][136];
    __shared__ float Bs_hi[16][72];
    __shared__ float Bs_lo[16][72];

    int b = blockIdx.z;
    const float* Ab  = A  + (size_t)b * sA;
    const float* A2b = SPLITA ? (A2 + (size_t)b * sA) : nullptr;
    const float* Bb  = Bm + (size_t)b * sB;
    float*       Cb  = C  + (size_t)b * sC;
    int m0 = blockIdx.y * 128, n0 = blockIdx.x * 64;
    int tid  = threadIdx.x;
    int wid  = tid >> 5, lane = tid & 31;
    int wm = (wid & 3) * 32;
    int wn = (wid >> 2) * 32;
    int lr = lane >> 2, lc = lane & 3;

    float acc[2][4][4];
    #pragma unroll
    for (int i = 0; i < 2; i++)
        #pragma unroll
        for (int j = 0; j < 4; j++)
            #pragma unroll
            for (int t = 0; t < 4; t++) acc[i][j][t] = 0.f;

    float aPre[8], bPre[4];

    auto gload = [&](int k0) {
        #pragma unroll
        for (int i = 0; i < 8; i++) {
            int linear = tid + i * 256;
            int mm, kk;
            if (AKC) { kk = linear & 15;  mm = linear >> 4; }
            else     { mm = linear & 127; kk = linear >> 7; }
            int gm = m0 + mm, gk = k0 + kk;
            float val = 0.f;
            if (gm < M) {
                if (SPLITA) {
                    val = (gk < Ksplit)
                        ? Ab [(size_t)gm * lda_m + (size_t)gk          * lda_k]
                        : A2b[(size_t)gm * lda_m + (size_t)(gk-Ksplit) * lda_k];
                } else {
                    val = Ab[(size_t)gm * lda_m + (size_t)gk * lda_k];
                }
            }
            aPre[i] = val;
        }
        #pragma unroll
        for (int i = 0; i < 4; i++) {
            int linear = tid + i * 256;
            int nn, kk;
            if (BKC) { kk = linear & 15; nn = linear >> 4; }
            else     { nn = linear & 63; kk = linear >> 6; }
            int gn = n0 + nn, gk = k0 + kk;
            float val = 0.f;
            if (gn < N) val = Bb[(size_t)gn * ldb_n + (size_t)gk * ldb_k];
            bPre[i] = val;
        }
    };
    auto stile = [&]() {
        #pragma unroll
        for (int i = 0; i < 8; i++) {
            int linear = tid + i * 256;
            int mm, kk;
            if (AKC) { kk = linear & 15;  mm = linear >> 4; }
            else     { mm = linear & 127; kk = linear >> 7; }
            float v = aPre[i];
            float h = tf32r(v);
            As_hi[kk][mm] = h;
            if (XA == 3) As_lo[kk][mm] = tf32r(v - h);
        }
        #pragma unroll
        for (int i = 0; i < 4; i++) {
            int linear = tid + i * 256;
            int nn, kk;
            if (BKC) { kk = linear & 15; nn = linear >> 4; }
            else     { nn = linear & 63; kk = linear >> 6; }
            float v = bPre[i];
            float h = tf32r(v);
            Bs_hi[kk][nn] = h;
            if (XA == 3) Bs_lo[kk][nn] = tf32r(v - h);
        }
    };

    gload(0);
    for (int k0 = 0; k0 < K; k0 += 16) {
        stile();
        __syncthreads();
        if (k0 + 16 < K) gload(k0 + 16);

        #pragma unroll
        for (int kt = 0; kt < 2; kt++) {
            int kb = kt * 8;
            uint32_t ah[2][4], al[2][4];
            #pragma unroll
            for (int mt = 0; mt < 2; mt++) {
                int mb = wm + mt * 16;
                ah[mt][0] = __float_as_uint(As_hi[kb+lc  ][mb+lr  ]);
                ah[mt][1] = __float_as_uint(As_hi[kb+lc  ][mb+lr+8]);
                ah[mt][2] = __float_as_uint(As_hi[kb+lc+4][mb+lr  ]);
                ah[mt][3] = __float_as_uint(As_hi[kb+lc+4][mb+lr+8]);
                if (XA == 3) {
                    al[mt][0] = __float_as_uint(As_lo[kb+lc  ][mb+lr  ]);
                    al[mt][1] = __float_as_uint(As_lo[kb+lc  ][mb+lr+8]);
                    al[mt][2] = __float_as_uint(As_lo[kb+lc+4][mb+lr  ]);
                    al[mt][3] = __float_as_uint(As_lo[kb+lc+4][mb+lr+8]);
                }
            }
            #pragma unroll
            for (int nt = 0; nt < 4; nt++) {
                int nb = wn + nt * 8;
                uint32_t b0 = __float_as_uint(Bs_hi[kb+lc  ][nb+lr]);
                uint32_t b1 = __float_as_uint(Bs_hi[kb+lc+4][nb+lr]);
                uint32_t l0 = 0, l1 = 0;
                if (XA == 3) {
                    l0 = __float_as_uint(Bs_lo[kb+lc  ][nb+lr]);
                    l1 = __float_as_uint(Bs_lo[kb+lc+4][nb+lr]);
                }
                #pragma unroll
                for (int mt = 0; mt < 2; mt++) {
                    if (XA == 3) {
                        mma_tf32(acc[mt][nt], ah[mt][0], ah[mt][1], ah[mt][2], ah[mt][3], l0, l1);
                        mma_tf32(acc[mt][nt], al[mt][0], al[mt][1], al[mt][2], al[mt][3], b0, b1);
                    }
                    mma_tf32(acc[mt][nt], ah[mt][0], ah[mt][1], ah[mt][2], ah[mt][3], b0, b1);
                }
            }
        }
        __syncthreads();
    }

    if (FUSEM) {
        unsigned* Mx = Mmax + (size_t)b * LL;
        float*    Ms = Msum + (size_t)b * LL;
        #pragma unroll
        for (int mt = 0; mt < 2; mt++) {
            float mx[2] = {-INFINITY, -INFINITY};
            float sm[2] = {0.f, 0.f};
            #pragma unroll
            for (int nt = 0; nt < 4; nt++) {
                int gc0 = n0 + wn + nt*8 + 2*lc;
                #pragma unroll
                for (int t = 0; t < 4; t++) {
                    int gn = gc0 + (t & 1);
                    int h = t >> 1;
                    if (gn < N) {
                        float v = acc[mt][nt][t];
                        mx[h] = fmaxf(mx[h], v);
                        sm[h] += v;
                    }
                }
            }
            #pragma unroll
            for (int o = 1; o <= 2; o <<= 1) {
                #pragma unroll
                for (int h = 0; h < 2; h++) {
                    mx[h] = fmaxf(mx[h], __shfl_xor_sync(0xFFFFFFFFu, mx[h], o));
                    sm[h] += __shfl_xor_sync(0xFFFFFFFFu, sm[h], o);
                }
            }
            if (lc == 0) {
                #pragma unroll
                for (int h = 0; h < 2; h++) {
                    int gm = m0 + wm + mt*16 + lr + h*8;
                    if (gm < M) {
                        atomicMax(&Mx[gm], fkey(mx[h]));
                        atomicAdd(&Ms[gm], sm[h]);
                    }
                }
            }
        }
    } else {
        #pragma unroll
        for (int mt = 0; mt < 2; mt++) {
            #pragma unroll
            for (int nt = 0; nt < 4; nt++) {
                int gr0 = m0 + wm + mt*16 + lr;
                int gc0 = n0 + wn + nt*8 + 2*lc;
                #pragma unroll
                for (int t = 0; t < 4; t++) {
                    int gm = gr0 + ((t >= 2) ? 8 : 0);
                    int gn = gc0 + (t & 1);
                    if (gm >= M || gn >= N) continue;
                    float v = acc[mt][nt][t] * alpha;
                    if (bias) v += bias[gn];
                    Cb[(size_t)gm * ldc_m + (size_t)gn * ldc_n] = v;
                }
            }
        }
    }
}

// -------- init fused M buffers --------
__global__ void minit_kernel() {
    int i = blockIdx.x * blockDim.x + threadIdx.x;
    if (i < BB * LL) { g_Mmax[i] = fkey(-INFINITY); g_Msum[i] = 0.f; }
}

// -------- gather sampled K rows --------
__global__ void gather_ksample_kernel(const int* __restrict__ idx, int U) {
    size_t t = (size_t)blockIdx.x * blockDim.x + threadIdx.x;
    size_t total = (size_t)BB * U * DD;
    if (t >= total) return;
    int d = (int)(t % DD);
    size_t rest = t / DD;
    int s = (int)(rest % U);
    int b = (int)(rest / U);
    g_ksamp[((size_t)b * U + s) * DD + d] = g_k[((size_t)b * LL + idx[s]) * DD + d];
}

// -------- top-k on cheap M + band extraction --------
__global__ void topk_band_kernel(int u) {
    __shared__ float sv[LL];
    __shared__ int   si[LL];
    __shared__ int sA, sB;
    int b = blockIdx.x;
    for (int i = threadIdx.x; i < LL; i += blockDim.x) {
        sv[i] = fdecode(g_Mmax[(size_t)b*LL + i]) - g_Msum[(size_t)b*LL + i] * (1.0f/(float)LL);
        si[i] = i;
    }
    __syncthreads();
    for (int k = 2; k <= LL; k <<= 1) {
        for (int j = k >> 1; j > 0; j >>= 1) {
            for (int t = threadIdx.x; t < LL; t += blockDim.x) {
                int ixj = t ^ j;
                if (ixj > t) {
                    bool dirDesc = ((t & k) == 0);
                    float va = sv[t], vb = sv[ixj];
                    int   ia = si[t], ib = si[ixj];
                    bool aBeforeB = (va > vb) || (va == vb && ia < ib);
                    bool swp = dirDesc ? !aBeforeB : aBeforeB;
                    if (swp) { sv[t] = vb; sv[ixj] = va; si[t] = ib; si[ixj] = ia; }
                }
            }
            __syncthreads();
        }
    }
    float theta = sv[u-1];
    float hiv = theta + BANDHW, lov = theta - BANDHW;
    if (threadIdx.x == 0) { sA = 0; sB = LL; }
    __syncthreads();
    for (int i = threadIdx.x; i < LL; i += blockDim.x) {
        if (sv[i] <= hiv && (i == 0 || sv[i-1] > hiv)) sA = i;
        if (sv[i] <  lov && (i == 0 || sv[i-1] >= lov)) sB = i;
    }
    __syncthreads();
    int a = sA;
    int len = sB - a; if (len > BANDCAP) len = BANDCAP;
    for (int i = threadIdx.x; i < u; i += blockDim.x) g_mtop[(size_t)b*u + i] = si[i];
    for (int j = threadIdx.x; j < len; j += blockDim.x) g_band[(size_t)b*BANDCAP + j] = si[a + j];
    if (threadIdx.x == 0) { g_bandinfo[b*2] = a; g_bandinfo[b*2+1] = len; }
}

// -------- exact M recompute for band rows (fp32 FFMA from stored q/ksamp) --------
__global__ void refine_kernel(int U) {
    __shared__ float qrow[DD];
    __shared__ float wmx[8], wsm[8];
    int b = blockIdx.y, pos = blockIdx.x;
    int len = g_bandinfo[b*2+1];
    if (pos >= len) return;
    int l = g_band[(size_t)b*BANDCAP + pos];
    const float* qp = g_q + ((size_t)b*LL + l)*DD;
    for (int d = threadIdx.x; d < DD; d += 256) qrow[d] = qp[d];
    __syncthreads();
    int wid = threadIdx.x >> 5, lane = threadIdx.x & 31;
    float mx = -INFINITY, sm = 0.f;
    for (int s = wid; s < U; s += 8) {
        const float* kr = g_ksamp + ((size_t)b*U + s)*DD;
        float p = 0.f;
        #pragma unroll 4
        for (int d = lane; d < DD; d += 32) p += qrow[d] * kr[d];
        #pragma unroll
        for (int o = 16; o; o >>= 1) p += __shfl_xor_sync(0xFFFFFFFFu, p, o);
        mx = fmaxf(mx, p);
        sm += p;
    }
    if (lane == 0) { wmx[wid] = mx; wsm[wid] = sm; }
    __syncthreads();
    if (threadIdx.x == 0) {
        float M = -INFINITY, S = 0.f;
        #pragma unroll
        for (int w = 0; w < 8; w++) { M = fmaxf(M, wmx[w]); S += wsm[w]; }
        g_Mexact[(size_t)b*BANDCAP + pos] = M - S * (1.0f/(float)LL);
    }
}

// -------- final selection: sure-in + best (u-a) of band by exact M --------
__global__ void select_kernel(int u) {
    __shared__ float sv[BANDCAP];
    __shared__ int   si[BANDCAP];
    int b = blockIdx.x;
    int a = g_bandinfo[b*2], len = g_bandinfo[b*2+1];
    for (int i = threadIdx.x; i < BANDCAP; i += blockDim.x) {
        if (i < len) { sv[i] = g_Mexact[(size_t)b*BANDCAP + i]; si[i] = g_band[(size_t)b*BANDCAP + i]; }
        else         { sv[i] = -INFINITY; si[i] = 0x7fffffff; }
    }
    __syncthreads();
    for (int k = 2; k <= BANDCAP; k <<= 1) {
        for (int j = k >> 1; j > 0; j >>= 1) {
            for (int t = threadIdx.x; t < BANDCAP; t += blockDim.x) {
                int ixj = t ^ j;
                if (ixj > t) {
                    bool dirDesc = ((t & k) == 0);
                    float va = sv[t], vb = sv[ixj];
                    int   ia = si[t], ib = si[ixj];
                    bool aBeforeB = (va > vb) || (va == vb && ia < ib);
                    bool swp = dirDesc ? !aBeforeB : aBeforeB;
                    if (swp) { sv[t] = vb; sv[ixj] = va; si[t] = ib; si[ixj] = ia; }
                }
            }
            __syncthreads();
        }
    }
    int need = u - a;
    for (int j = threadIdx.x; j < need; j += blockDim.x)
        g_mtop[(size_t)b*u + a + j] = si[j];
}

// -------- gather Q_reduce rows --------
__global__ void gather_qr_kernel(int u) {
    size_t t = (size_t)blockIdx.x * blockDim.x + threadIdx.x;
    size_t total = (size_t)BB * u * DD;
    if (t >= total) return;
    int d = (int)(t % DD);
    size_t rest = t / DD;
    int uu = (int)(rest % u);
    int b  = (int)(rest / u);
    int l = g_mtop[(size_t)b*u + uu];
    g_qr[((size_t)b*u + uu) * DD + d] = g_q[((size_t)b*LL + l) * DD + d];
}

// -------- row softmax over L --------
__global__ void softmax_kernel() {
    __shared__ float row[LL];
    __shared__ float red[256];
    size_t r = blockIdx.x;
    float* ptr = g_scores + r * (size_t)LL;
    float mx = -INFINITY;
    for (int i = threadIdx.x; i < LL; i += 256) { float x = ptr[i]; row[i] = x; mx = fmaxf(mx, x); }
    red[threadIdx.x] = mx; __syncthreads();
    for (int s = 128; s; s >>= 1) { if (threadIdx.x < s) red[threadIdx.x] = fmaxf(red[threadIdx.x], red[threadIdx.x+s]); __syncthreads(); }
    mx = red[0]; __syncthreads();
    float sm = 0.f;
    for (int i = threadIdx.x; i < LL; i += 256) { float e = __expf(row[i] - mx); row[i] = e; sm += e; }
    red[threadIdx.x] = sm; __syncthreads();
    for (int s = 128; s; s >>= 1) { if (threadIdx.x < s) red[threadIdx.x] += red[threadIdx.x+s]; __syncthreads(); }
    float inv = 1.f / red[0];
    for (int i = threadIdx.x; i < LL; i += 256) ptr[i] = row[i] * inv;
}

// -------- v mean over L --------
__global__ void vmean_zero_kernel() {
    int i = blockIdx.x * blockDim.x + threadIdx.x;
    if (i < BB * DD) g_vmean[i] = 0.f;
}
__global__ void vmean_kernel() {
    int b = blockIdx.x, ch = blockIdx.y;
    int d = threadIdx.x;
    float s = 0.f;
    int l0 = ch * 128;
    for (int l = l0; l < l0 + 128; l++) s += g_v[((size_t)b*LL + l) * DD + d];
    atomicAdd(&g_vmean[b*DD + d], s * (1.0f / (float)LL));
}

// -------- output: broadcast mean then scatter updated rows --------
__global__ void broadcast_out_kernel(float* __restrict__ out) {
    size_t t = (size_t)blockIdx.x * blockDim.x + threadIdx.x;
    if (t >= (size_t)BB*LL*DD) return;
    int d = (int)(t % DD);
    int b = (int)(t / ((size_t)LL*DD));
    out[t] = g_vmean[b*DD + d];
}
__global__ void scatter_out_kernel(float* __restrict__ out, int u) {
    size_t t = (size_t)blockIdx.x * blockDim.x + threadIdx.x;
    size_t total = (size_t)BB * u * DD;
    if (t >= total) return;
    int d = (int)(t % DD);
    size_t rest = t / DD;
    int uu = (int)(rest % u);
    int b  = (int)(rest / u);
    int l = g_mtop[(size_t)b*u + uu];
    out[((size_t)b*LL + l) * DD + d] = g_upd[((size_t)b*u + uu) * DD + d];
}

extern "C" void kernel_launch(void* const* d_in, const int* in_sizes, int n_in,
                              void* d_out, int out_size)
{
    const float* in1 = (const float*)d_in[0];
    const float* in2 = (const float*)d_in[1];
    const float* Wq  = (const float*)d_in[2];
    const float* bq  = (const float*)d_in[3];
    const float* Wk  = (const float*)d_in[4];
    const float* bk  = (const float*)d_in[5];
    const float* Wv  = (const float*)d_in[6];
    const float* bv  = (const float*)d_in[7];
    const int*   idx = (const int*)d_in[8];
    int U = in_sizes[8];
    int u = (U < LL) ? U : LL;
    float* out = (float*)d_out;

    float *q, *k, *v, *ksamp, *qr, *scores, *upd;
    unsigned* mmax; float* msum;
    cudaGetSymbolAddress((void**)&q,      g_q);
    cudaGetSymbolAddress((void**)&k,      g_k);
    cudaGetSymbolAddress((void**)&v,      g_v);
    cudaGetSymbolAddress((void**)&ksamp,  g_ksamp);
    cudaGetSymbolAddress((void**)&qr,     g_qr);
    cudaGetSymbolAddress((void**)&scores, g_scores);
    cudaGetSymbolAddress((void**)&upd,    g_upd);
    cudaGetSymbolAddress((void**)&mmax,   g_Mmax);
    cudaGetSymbolAddress((void**)&msum,   g_Msum);

    dim3 blk(256);
    const float scale = rsqrtf(512.0f);  // 1/sqrt(IN_CHANNELS)

    // 1) projections (R9 layout): q,k 3xTF32 (selection + refine source); v 1xTF32.
    //    y[o*L+s] flat IS the (L,D)-row-major q/k/v view after the reference reshape.
    {
        dim3 grid(DD/64, LL/128, BB);
        gemm_tc_kernel<false,true,true,3,false><<<grid, blk>>>(in1, in2, Wq, q, LL, DD, CC, CIN,
            1L, (long)LL, (long)CC, 1L, 1L, (long)LL, (long)CIN*LL, 0L, (long)LL*DD, bq, 1.0f, nullptr, nullptr);
        gemm_tc_kernel<false,true,true,3,false><<<grid, blk>>>(in1, in2, Wk, k, LL, DD, CC, CIN,
            1L, (long)LL, (long)CC, 1L, 1L, (long)LL, (long)CIN*LL, 0L, (long)LL*DD, bk, 1.0f, nullptr, nullptr);
        gemm_tc_kernel<false,true,true,1,false><<<grid, blk>>>(in1, in2, Wv, v, LL, DD, CC, CIN,
            1L, (long)LL, (long)CC, 1L, 1L, (long)LL, (long)CIN*LL, 0L, (long)LL*DD, bv, 1.0f, nullptr, nullptr);
    }

    // 2) gather sampled K rows + init M buffers
    {
        size_t total = (size_t)BB * U * DD;
        gather_ksample_kernel<<<(unsigned)((total + 255) / 256), blk>>>(idx, U);
        minit_kernel<<<(BB*LL + 255)/256, blk>>>();
    }

    // 3) cheap QKs fused with M-stats (1xTF32; band-refined below)
    {
        dim3 grid((U + 63)/64, LL/128, BB);
        gemm_tc_kernel<true,true,false,1,true><<<grid, blk>>>(q, nullptr, ksamp, nullptr, LL, U, DD, 0,
            (long)DD, 1L, (long)DD, 1L, 0L, 0L, (long)LL*DD, (long)U*DD, 0L, nullptr, 1.0f, mmax, msum);
    }

    // 4) top-k on cheap M + band; exact fp32 refine of band; final set selection
    topk_band_kernel<<<BB, 1024>>>(u);
    {
        dim3 grid(BANDCAP, BB);
        refine_kernel<<<grid, blk>>>(U);
    }
    select_kernel<<<BB, 1024>>>(u);

    // 5) gather Q_reduce
    {
        size_t total = (size_t)BB * u * DD;
        gather_qr_kernel<<<(unsigned)((total + 255) / 256), blk>>>(u);
    }

    // 6) scores[uu,l] = (Qr[uu,:] . k[l,:]) * scale   (1xTF32)
    {
        dim3 grid(LL/64, (u + 127)/128, BB);
        gemm_tc_kernel<true,true,false,1,false><<<grid, blk>>>(qr, nullptr, k, scores, u, LL, DD, 0,
            (long)DD, 1L, (long)DD, 1L, (long)LL, 1L, (long)u*DD, (long)LL*DD, (long)u*LL, nullptr, scale, nullptr, nullptr);
    }

    // 7) softmax over L (in place)
    softmax_kernel<<<BB*u, blk>>>();

    // 8) upd[uu,d] = sum_l attn[uu,l]*v[l,d]   (1xTF32)
    {
        dim3 grid(DD/64, (u + 127)/128, BB);
        gemm_tc_kernel<true,false,false,1,false><<<grid, blk>>>(scores, nullptr, v, upd, u, DD, LL, 0,
            (long)LL, 1L, 1L, (long)DD, (long)DD, 1L, (long)u*LL, (long)LL*DD, (long)u*DD, nullptr, 1.0f, nullptr, nullptr);
    }

    // 9) v mean, broadcast, scatter
    vmean_zero_kernel<<<(BB*DD + 255)/256, blk>>>();
    {
        dim3 grid(BB, 32);
        vmean_kernel<<<grid, DD>>>();
    }
    {
        size_t total = (size_t)BB * LL * DD;
        broadcast_out_kernel<<<(unsigned)((total + 255)/256), blk>>>(out);
        size_t st = (size_t)BB * u * DD;
        scatter_out_kernel<<<(unsigned)((st + 255)/256), blk>>>(out, u);
    }
}

// round 16
// speedup vs baseline: 1.5014x; 1.0422x over previous
#include <cuda_runtime.h>
#include <math.h>
#include <stdint.h>

#define BB   16
#define CIN  256
#define CC   512
#define LL   4096
#define DD   512
#define UMAX 512
#define BANDCAP 1024
#define BANDHW  0.04f

// -------- scratch (device globals; allocation-free) --------
__device__ float    g_q[(size_t)BB*LL*DD];
__device__ float    g_k[(size_t)BB*LL*DD];
__device__ float    g_v[(size_t)BB*LL*DD];
__device__ float    g_ksamp[(size_t)BB*UMAX*DD];
__device__ unsigned g_Mmax[(size_t)BB*LL];
__device__ float    g_Msum[(size_t)BB*LL];
__device__ int      g_mtop[(size_t)BB*UMAX];
__device__ int      g_band[(size_t)BB*BANDCAP];
__device__ float    g_Mexact[(size_t)BB*BANDCAP];
__device__ int      g_bandinfo[BB*2];           // {sure_in_count a, band_len}
__device__ float    g_qr[(size_t)BB*UMAX*DD];
__device__ float    g_scores[(size_t)BB*UMAX*LL];
__device__ float    g_vmean[(size_t)BB*DD];
__device__ float    g_upd[(size_t)BB*UMAX*DD];

// -------- tf32 helpers --------
__device__ __forceinline__ float tf32r(float a) {
    uint32_t r;
    asm("cvt.rna.tf32.f32 %0, %1;" : "=r"(r) : "f"(a));
    return __uint_as_float(r);
}
__device__ __forceinline__ void mma_tf32(float c[4],
                                         uint32_t a0, uint32_t a1, uint32_t a2, uint32_t a3,
                                         uint32_t b0, uint32_t b1) {
    asm("mma.sync.aligned.m16n8k8.row.col.f32.tf32.tf32.f32 "
        "{%0,%1,%2,%3},{%4,%5,%6,%7},{%8,%9},{%0,%1,%2,%3};"
        : "+f"(c[0]), "+f"(c[1]), "+f"(c[2]), "+f"(c[3])
        : "r"(a0), "r"(a1), "r"(a2), "r"(a3), "r"(b0), "r"(b1));
}
__device__ __forceinline__ unsigned fkey(float f) {
    unsigned u = __float_as_uint(f);
    return (u & 0x80000000u) ? ~u : (u | 0x80000000u);
}
__device__ __forceinline__ float fdecode(unsigned k) {
    return (k & 0x80000000u) ? __uint_as_float(k ^ 0x80000000u) : __uint_as_float(~k);
}

// ======== generic tiled GEMM (R9-proven), 128x64 block, 8 warps, 32x32 warp tile ========
// C[gm*ldc_m + gn*ldc_n] = alpha * sum_k A * B (+ bias[n]); XA=3: 3xTF32; XA=1: plain.
// FUSEM: per-row max & sum atomically merged into Mmax/Msum instead of C write.
template<bool AKC, bool BKC, bool SPLITA, int XA, bool FUSEM>
__global__ void __launch_bounds__(256)
gemm_tc_kernel(const float* __restrict__ A, const float* __restrict__ A2,
               const float* __restrict__ Bm, float* __restrict__ C,
               int M, int N, int K, int Ksplit,
               long lda_m, long lda_k, long ldb_n, long ldb_k,
               long ldc_m, long ldc_n,
               long sA, long sB, long sC,
               const float* __restrict__ bias, float alpha,
               unsigned* __restrict__ Mmax, float* __restrict__ Msum)
{
    __shared__ float As_hi[16][136];
    __shared__ float As_lo[16][136];
    __shared__ float Bs_hi[16][72];
    __shared__ float Bs_lo[16][72];

    int b = blockIdx.z;
    const float* Ab  = A  + (size_t)b * sA;
    const float* A2b = SPLITA ? (A2 + (size_t)b * sA) : nullptr;
    const float* Bb  = Bm + (size_t)b * sB;
    float*       Cb  = C  + (size_t)b * sC;
    int m0 = blockIdx.y * 128, n0 = blockIdx.x * 64;
    int tid  = threadIdx.x;
    int wid  = tid >> 5, lane = tid & 31;
    int wm = (wid & 3) * 32;
    int wn = (wid >> 2) * 32;
    int lr = lane >> 2, lc = lane & 3;

    float acc[2][4][4];
    #pragma unroll
    for (int i = 0; i < 2; i++)
        #pragma unroll
        for (int j = 0; j < 4; j++)
            #pragma unroll
            for (int t = 0; t < 4; t++) acc[i][j][t] = 0.f;

    float aPre[8], bPre[4];

    auto gload = [&](int k0) {
        #pragma unroll
        for (int i = 0; i < 8; i++) {
            int linear = tid + i * 256;
            int mm, kk;
            if (AKC) { kk = linear & 15;  mm = linear >> 4; }
            else     { mm = linear & 127; kk = linear >> 7; }
            int gm = m0 + mm, gk = k0 + kk;
            float val = 0.f;
            if (gm < M) {
                if (SPLITA) {
                    val = (gk < Ksplit)
                        ? Ab [(size_t)gm * lda_m + (size_t)gk          * lda_k]
                        : A2b[(size_t)gm * lda_m + (size_t)(gk-Ksplit) * lda_k];
                } else {
                    val = Ab[(size_t)gm * lda_m + (size_t)gk * lda_k];
                }
            }
            aPre[i] = val;
        }
        #pragma unroll
        for (int i = 0; i < 4; i++) {
            int linear = tid + i * 256;
            int nn, kk;
            if (BKC) { kk = linear & 15; nn = linear >> 4; }
            else     { nn = linear & 63; kk = linear >> 6; }
            int gn = n0 + nn, gk = k0 + kk;
            float val = 0.f;
            if (gn < N) val = Bb[(size_t)gn * ldb_n + (size_t)gk * ldb_k];
            bPre[i] = val;
        }
    };
    auto stile = [&]() {
        #pragma unroll
        for (int i = 0; i < 8; i++) {
            int linear = tid + i * 256;
            int mm, kk;
            if (AKC) { kk = linear & 15;  mm = linear >> 4; }
            else     { mm = linear & 127; kk = linear >> 7; }
            float v = aPre[i];
            float h = tf32r(v);
            As_hi[kk][mm] = h;
            if (XA == 3) As_lo[kk][mm] = tf32r(v - h);
        }
        #pragma unroll
        for (int i = 0; i < 4; i++) {
            int linear = tid + i * 256;
            int nn, kk;
            if (BKC) { kk = linear & 15; nn = linear >> 4; }
            else     { nn = linear & 63; kk = linear >> 6; }
            float v = bPre[i];
            float h = tf32r(v);
            Bs_hi[kk][nn] = h;
            if (XA == 3) Bs_lo[kk][nn] = tf32r(v - h);
        }
    };

    gload(0);
    for (int k0 = 0; k0 < K; k0 += 16) {
        stile();
        __syncthreads();
        if (k0 + 16 < K) gload(k0 + 16);

        #pragma unroll
        for (int kt = 0; kt < 2; kt++) {
            int kb = kt * 8;
            uint32_t ah[2][4], al[2][4];
            #pragma unroll
            for (int mt = 0; mt < 2; mt++) {
                int mb = wm + mt * 16;
                ah[mt][0] = __float_as_uint(As_hi[kb+lc  ][mb+lr  ]);
                ah[mt][1] = __float_as_uint(As_hi[kb+lc  ][mb+lr+8]);
                ah[mt][2] = __float_as_uint(As_hi[kb+lc+4][mb+lr  ]);
                ah[mt][3] = __float_as_uint(As_hi[kb+lc+4][mb+lr+8]);
                if (XA == 3) {
                    al[mt][0] = __float_as_uint(As_lo[kb+lc  ][mb+lr  ]);
                    al[mt][1] = __float_as_uint(As_lo[kb+lc  ][mb+lr+8]);
                    al[mt][2] = __float_as_uint(As_lo[kb+lc+4][mb+lr  ]);
                    al[mt][3] = __float_as_uint(As_lo[kb+lc+4][mb+lr+8]);
                }
            }
            #pragma unroll
            for (int nt = 0; nt < 4; nt++) {
                int nb = wn + nt * 8;
                uint32_t b0 = __float_as_uint(Bs_hi[kb+lc  ][nb+lr]);
                uint32_t b1 = __float_as_uint(Bs_hi[kb+lc+4][nb+lr]);
                uint32_t l0 = 0, l1 = 0;
                if (XA == 3) {
                    l0 = __float_as_uint(Bs_lo[kb+lc  ][nb+lr]);
                    l1 = __float_as_uint(Bs_lo[kb+lc+4][nb+lr]);
                }
                #pragma unroll
                for (int mt = 0; mt < 2; mt++) {
                    if (XA == 3) {
                        mma_tf32(acc[mt][nt], ah[mt][0], ah[mt][1], ah[mt][2], ah[mt][3], l0, l1);
                        mma_tf32(acc[mt][nt], al[mt][0], al[mt][1], al[mt][2], al[mt][3], b0, b1);
                    }
                    mma_tf32(acc[mt][nt], ah[mt][0], ah[mt][1], ah[mt][2], ah[mt][3], b0, b1);
                }
            }
        }
        __syncthreads();
    }

    if (FUSEM) {
        unsigned* Mx = Mmax + (size_t)b * LL;
        float*    Ms = Msum + (size_t)b * LL;
        #pragma unroll
        for (int mt = 0; mt < 2; mt++) {
            float mx[2] = {-INFINITY, -INFINITY};
            float sm[2] = {0.f, 0.f};
            #pragma unroll
            for (int nt = 0; nt < 4; nt++) {
                int gc0 = n0 + wn + nt*8 + 2*lc;
                #pragma unroll
                for (int t = 0; t < 4; t++) {
                    int gn = gc0 + (t & 1);
                    int h = t >> 1;
                    if (gn < N) {
                        float v = acc[mt][nt][t];
                        mx[h] = fmaxf(mx[h], v);
                        sm[h] += v;
                    }
                }
            }
            #pragma unroll
            for (int o = 1; o <= 2; o <<= 1) {
                #pragma unroll
                for (int h = 0; h < 2; h++) {
                    mx[h] = fmaxf(mx[h], __shfl_xor_sync(0xFFFFFFFFu, mx[h], o));
                    sm[h] += __shfl_xor_sync(0xFFFFFFFFu, sm[h], o);
                }
            }
            if (lc == 0) {
                #pragma unroll
                for (int h = 0; h < 2; h++) {
                    int gm = m0 + wm + mt*16 + lr + h*8;
                    if (gm < M) {
                        atomicMax(&Mx[gm], fkey(mx[h]));
                        atomicAdd(&Ms[gm], sm[h]);
                    }
                }
            }
        }
    } else {
        #pragma unroll
        for (int mt = 0; mt < 2; mt++) {
            #pragma unroll
            for (int nt = 0; nt < 4; nt++) {
                int gr0 = m0 + wm + mt*16 + lr;
                int gc0 = n0 + wn + nt*8 + 2*lc;
                #pragma unroll
                for (int t = 0; t < 4; t++) {
                    int gm = gr0 + ((t >= 2) ? 8 : 0);
                    int gn = gc0 + (t & 1);
                    if (gm >= M || gn >= N) continue;
                    float v = acc[mt][nt][t] * alpha;
                    if (bias) v += bias[gn];
                    Cb[(size_t)gm * ldc_m + (size_t)gn * ldc_n] = v;
                }
            }
        }
    }
}

// -------- init fused M buffers --------
__global__ void minit_kernel() {
    int i = blockIdx.x * blockDim.x + threadIdx.x;
    if (i < BB * LL) { g_Mmax[i] = fkey(-INFINITY); g_Msum[i] = 0.f; }
}

// -------- gather sampled K rows --------
__global__ void gather_ksample_kernel(const int* __restrict__ idx, int U) {
    size_t t = (size_t)blockIdx.x * blockDim.x + threadIdx.x;
    size_t total = (size_t)BB * U * DD;
    if (t >= total) return;
    int d = (int)(t % DD);
    size_t rest = t / DD;
    int s = (int)(rest % U);
    int b = (int)(rest / U);
    g_ksamp[((size_t)b * U + s) * DD + d] = g_k[((size_t)b * LL + idx[s]) * DD + d];
}

// -------- top-k on cheap M + band extraction --------
__global__ void topk_band_kernel(int u) {
    __shared__ float sv[LL];
    __shared__ int   si[LL];
    __shared__ int sA, sB;
    int b = blockIdx.x;
    for (int i = threadIdx.x; i < LL; i += blockDim.x) {
        sv[i] = fdecode(g_Mmax[(size_t)b*LL + i]) - g_Msum[(size_t)b*LL + i] * (1.0f/(float)LL);
        si[i] = i;
    }
    __syncthreads();
    for (int k = 2; k <= LL; k <<= 1) {
        for (int j = k >> 1; j > 0; j >>= 1) {
            for (int t = threadIdx.x; t < LL; t += blockDim.x) {
                int ixj = t ^ j;
                if (ixj > t) {
                    bool dirDesc = ((t & k) == 0);
                    float va = sv[t], vb = sv[ixj];
                    int   ia = si[t], ib = si[ixj];
                    bool aBeforeB = (va > vb) || (va == vb && ia < ib);
                    bool swp = dirDesc ? !aBeforeB : aBeforeB;
                    if (swp) { sv[t] = vb; sv[ixj] = va; si[t] = ib; si[ixj] = ia; }
                }
            }
            __syncthreads();
        }
    }
    float theta = sv[u-1];
    float hiv = theta + BANDHW, lov = theta - BANDHW;
    if (threadIdx.x == 0) { sA = 0; sB = LL; }
    __syncthreads();
    for (int i = threadIdx.x; i < LL; i += blockDim.x) {
        if (sv[i] <= hiv && (i == 0 || sv[i-1] > hiv)) sA = i;
        if (sv[i] <  lov && (i == 0 || sv[i-1] >= lov)) sB = i;
    }
    __syncthreads();
    int a = sA;
    int len = sB - a; if (len > BANDCAP) len = BANDCAP;
    for (int i = threadIdx.x; i < u; i += blockDim.x) g_mtop[(size_t)b*u + i] = si[i];
    for (int j = threadIdx.x; j < len; j += blockDim.x) g_band[(size_t)b*BANDCAP + j] = si[a + j];
    if (threadIdx.x == 0) { g_bandinfo[b*2] = a; g_bandinfo[b*2+1] = len; }
}

// -------- exact M for band rows: recompute q row from x (fp32), dot with ksamp --------
__global__ void refine_kernel(const float* __restrict__ in1, const float* __restrict__ in2,
                              const float* __restrict__ Wq, const float* __restrict__ bq,
                              int U) {
    __shared__ float wrow[CC];
    __shared__ float qrow[DD];
    __shared__ float wmx[8], wsm[8];
    int b = blockIdx.y, pos = blockIdx.x;
    int len = g_bandinfo[b*2+1];
    if (pos >= len) return;
    int l = g_band[(size_t)b*BANDCAP + pos];
    int o = l >> 3;            // output channel
    int r = l & 7;             // spatial slice index
    // Wq row into smem
    for (int c = threadIdx.x; c < CC; c += 256) wrow[c] = Wq[(size_t)o * CC + c];
    __syncthreads();
    // exact q row: q[l,d] = sum_c x[b,c,r*512+d] * Wq[o,c] + bq[o]
    const float* x1 = in1 + (size_t)b * CIN * LL + (size_t)r * 512;
    const float* x2 = in2 + (size_t)b * CIN * LL + (size_t)r * 512;
    float bqo = bq[o];
    #pragma unroll
    for (int half = 0; half < 2; half++) {
        int d = threadIdx.x + half * 256;
        float acc = bqo;
        #pragma unroll 4
        for (int c = 0; c < CIN; c++) acc += x1[(size_t)c * LL + d] * wrow[c];
        #pragma unroll 4
        for (int c = 0; c < CIN; c++) acc += x2[(size_t)c * LL + d] * wrow[CIN + c];
        qrow[d] = acc;
    }
    __syncthreads();
    // M = max_s - sum_s/L of qrow . ksamp[s]
    int wid = threadIdx.x >> 5, lane = threadIdx.x & 31;
    float mx = -INFINITY, sm = 0.f;
    for (int s = wid; s < U; s += 8) {
        const float* kr = g_ksamp + ((size_t)b*U + s)*DD;
        float p = 0.f;
        #pragma unroll 4
        for (int d = lane; d < DD; d += 32) p += qrow[d] * kr[d];
        #pragma unroll
        for (int off = 16; off; off >>= 1) p += __shfl_xor_sync(0xFFFFFFFFu, p, off);
        mx = fmaxf(mx, p);
        sm += p;
    }
    if (lane == 0) { wmx[wid] = mx; wsm[wid] = sm; }
    __syncthreads();
    if (threadIdx.x == 0) {
        float M = -INFINITY, S = 0.f;
        #pragma unroll
        for (int w = 0; w < 8; w++) { M = fmaxf(M, wmx[w]); S += wsm[w]; }
        g_Mexact[(size_t)b*BANDCAP + pos] = M - S * (1.0f/(float)LL);
    }
}

// -------- final selection: sure-in + best (u-a) of band by exact M --------
__global__ void select_kernel(int u) {
    __shared__ float sv[BANDCAP];
    __shared__ int   si[BANDCAP];
    int b = blockIdx.x;
    int a = g_bandinfo[b*2], len = g_bandinfo[b*2+1];
    for (int i = threadIdx.x; i < BANDCAP; i += blockDim.x) {
        if (i < len) { sv[i] = g_Mexact[(size_t)b*BANDCAP + i]; si[i] = g_band[(size_t)b*BANDCAP + i]; }
        else         { sv[i] = -INFINITY; si[i] = 0x7fffffff; }
    }
    __syncthreads();
    for (int k = 2; k <= BANDCAP; k <<= 1) {
        for (int j = k >> 1; j > 0; j >>= 1) {
            for (int t = threadIdx.x; t < BANDCAP; t += blockDim.x) {
                int ixj = t ^ j;
                if (ixj > t) {
                    bool dirDesc = ((t & k) == 0);
                    float va = sv[t], vb = sv[ixj];
                    int   ia = si[t], ib = si[ixj];
                    bool aBeforeB = (va > vb) || (va == vb && ia < ib);
                    bool swp = dirDesc ? !aBeforeB : aBeforeB;
                    if (swp) { sv[t] = vb; sv[ixj] = va; si[t] = ib; si[ixj] = ia; }
                }
            }
            __syncthreads();
        }
    }
    int need = u - a;
    for (int j = threadIdx.x; j < need; j += blockDim.x)
        g_mtop[(size_t)b*u + a + j] = si[j];
}

// -------- gather Q_reduce rows --------
__global__ void gather_qr_kernel(int u) {
    size_t t = (size_t)blockIdx.x * blockDim.x + threadIdx.x;
    size_t total = (size_t)BB * u * DD;
    if (t >= total) return;
    int d = (int)(t % DD);
    size_t rest = t / DD;
    int uu = (int)(rest % u);
    int b  = (int)(rest / u);
    int l = g_mtop[(size_t)b*u + uu];
    g_qr[((size_t)b*u + uu) * DD + d] = g_q[((size_t)b*LL + l) * DD + d];
}

// -------- row softmax over L --------
__global__ void softmax_kernel() {
    __shared__ float row[LL];
    __shared__ float red[256];
    size_t r = blockIdx.x;
    float* ptr = g_scores + r * (size_t)LL;
    float mx = -INFINITY;
    for (int i = threadIdx.x; i < LL; i += 256) { float x = ptr[i]; row[i] = x; mx = fmaxf(mx, x); }
    red[threadIdx.x] = mx; __syncthreads();
    for (int s = 128; s; s >>= 1) { if (threadIdx.x < s) red[threadIdx.x] = fmaxf(red[threadIdx.x], red[threadIdx.x+s]); __syncthreads(); }
    mx = red[0]; __syncthreads();
    float sm = 0.f;
    for (int i = threadIdx.x; i < LL; i += 256) { float e = __expf(row[i] - mx); row[i] = e; sm += e; }
    red[threadIdx.x] = sm; __syncthreads();
    for (int s = 128; s; s >>= 1) { if (threadIdx.x < s) red[threadIdx.x] += red[threadIdx.x+s]; __syncthreads(); }
    float inv = 1.f / red[0];
    for (int i = threadIdx.x; i < LL; i += 256) ptr[i] = row[i] * inv;
}

// -------- v mean over L --------
__global__ void vmean_zero_kernel() {
    int i = blockIdx.x * blockDim.x + threadIdx.x;
    if (i < BB * DD) g_vmean[i] = 0.f;
}
__global__ void vmean_kernel() {
    int b = blockIdx.x, ch = blockIdx.y;
    int d = threadIdx.x;
    float s = 0.f;
    int l0 = ch * 128;
    for (int l = l0; l < l0 + 128; l++) s += g_v[((size_t)b*LL + l) * DD + d];
    atomicAdd(&g_vmean[b*DD + d], s * (1.0f / (float)LL));
}

// -------- output: broadcast mean then scatter updated rows --------
__global__ void broadcast_out_kernel(float* __restrict__ out) {
    size_t t = (size_t)blockIdx.x * blockDim.x + threadIdx.x;
    if (t >= (size_t)BB*LL*DD) return;
    int d = (int)(t % DD);
    int b = (int)(t / ((size_t)LL*DD));
    out[t] = g_vmean[b*DD + d];
}
__global__ void scatter_out_kernel(float* __restrict__ out, int u) {
    size_t t = (size_t)blockIdx.x * blockDim.x + threadIdx.x;
    size_t total = (size_t)BB * u * DD;
    if (t >= total) return;
    int d = (int)(t % DD);
    size_t rest = t / DD;
    int uu = (int)(rest % u);
    int b  = (int)(rest / u);
    int l = g_mtop[(size_t)b*u + uu];
    out[((size_t)b*LL + l) * DD + d] = g_upd[((size_t)b*u + uu) * DD + d];
}

extern "C" void kernel_launch(void* const* d_in, const int* in_sizes, int n_in,
                              void* d_out, int out_size)
{
    const float* in1 = (const float*)d_in[0];
    const float* in2 = (const float*)d_in[1];
    const float* Wq  = (const float*)d_in[2];
    const float* bq  = (const float*)d_in[3];
    const float* Wk  = (const float*)d_in[4];
    const float* bk  = (const float*)d_in[5];
    const float* Wv  = (const float*)d_in[6];
    const float* bv  = (const float*)d_in[7];
    const int*   idx = (const int*)d_in[8];
    int U = in_sizes[8];
    int u = (U < LL) ? U : LL;
    float* out = (float*)d_out;

    float *q, *k, *v, *ksamp, *qr, *scores, *upd;
    unsigned* mmax; float* msum;
    cudaGetSymbolAddress((void**)&q,      g_q);
    cudaGetSymbolAddress((void**)&k,      g_k);
    cudaGetSymbolAddress((void**)&v,      g_v);
    cudaGetSymbolAddress((void**)&ksamp,  g_ksamp);
    cudaGetSymbolAddress((void**)&qr,     g_qr);
    cudaGetSymbolAddress((void**)&scores, g_scores);
    cudaGetSymbolAddress((void**)&upd,    g_upd);
    cudaGetSymbolAddress((void**)&mmax,   g_Mmax);
    cudaGetSymbolAddress((void**)&msum,   g_Msum);

    dim3 blk(256);
    const float scale = rsqrtf(512.0f);  // 1/sqrt(IN_CHANNELS)

    // 1) projections: q 1xTF32 (selection via band refine; scores are 1x anyway),
    //    k 3xTF32 (ksamp source must be exact), v 1xTF32.
    //    y[o*L+s] flat IS the (L,D)-row-major q/k/v view after the reference reshape.
    {
        dim3 grid(DD/64, LL/128, BB);
        gemm_tc_kernel<false,true,true,1,false><<<grid, blk>>>(in1, in2, Wq, q, LL, DD, CC, CIN,
            1L, (long)LL, (long)CC, 1L, 1L, (long)LL, (long)CIN*LL, 0L, (long)LL*DD, bq, 1.0f, nullptr, nullptr);
        gemm_tc_kernel<false,true,true,3,false><<<grid, blk>>>(in1, in2, Wk, k, LL, DD, CC, CIN,
            1L, (long)LL, (long)CC, 1L, 1L, (long)LL, (long)CIN*LL, 0L, (long)LL*DD, bk, 1.0f, nullptr, nullptr);
        gemm_tc_kernel<false,true,true,1,false><<<grid, blk>>>(in1, in2, Wv, v, LL, DD, CC, CIN,
            1L, (long)LL, (long)CC, 1L, 1L, (long)LL, (long)CIN*LL, 0L, (long)LL*DD, bv, 1.0f, nullptr, nullptr);
    }

    // 2) gather sampled K rows + init M buffers
    {
        size_t total = (size_t)BB * U * DD;
        gather_ksample_kernel<<<(unsigned)((total + 255) / 256), blk>>>(idx, U);
        minit_kernel<<<(BB*LL + 255)/256, blk>>>();
    }

    // 3) cheap QKs fused with M-stats (1xTF32; band-refined below)
    {
        dim3 grid((U + 63)/64, LL/128, BB);
        gemm_tc_kernel<true,true,false,1,true><<<grid, blk>>>(q, nullptr, ksamp, nullptr, LL, U, DD, 0,
            (long)DD, 1L, (long)DD, 1L, 0L, 0L, (long)LL*DD, (long)U*DD, 0L, nullptr, 1.0f, mmax, msum);
    }

    // 4) top-k on cheap M + band; exact refine (q recomputed from x); final selection
    topk_band_kernel<<<BB, 1024>>>(u);
    {
        dim3 grid(BANDCAP, BB);
        refine_kernel<<<grid, blk>>>(in1, in2, Wq, bq, U);
    }
    select_kernel<<<BB, 1024>>>(u);

    // 5) gather Q_reduce
    {
        size_t total = (size_t)BB * u * DD;
        gather_qr_kernel<<<(unsigned)((total + 255) / 256), blk>>>(u);
    }

    // 6) scores[uu,l] = (Qr[uu,:] . k[l,:]) * scale   (1xTF32)
    {
        dim3 grid(LL/64, (u + 127)/128, BB);
        gemm_tc_kernel<true,true,false,1,false><<<grid, blk>>>(qr, nullptr, k, scores, u, LL, DD, 0,
            (long)DD, 1L, (long)DD, 1L, (long)LL, 1L, (long)u*DD, (long)LL*DD, (long)u*LL, nullptr, scale, nullptr, nullptr);
    }

    // 7) softmax over L (in place)
    softmax_kernel<<<BB*u, blk>>>();

    // 8) upd[uu,d] = sum_l attn[uu,l]*v[l,d]   (1xTF32)
    {
        dim3 grid(DD/64, (u + 127)/128, BB);
        gemm_tc_kernel<true,false,false,1,false><<<grid, blk>>>(scores, nullptr, v, upd, u, DD, LL, 0,
            (long)LL, 1L, 1L, (long)DD, (long)DD, 1L, (long)u*LL, (long)LL*DD, (long)u*DD, nullptr, 1.0f, nullptr, nullptr);
    }

    // 9) v mean, broadcast, scatter
    vmean_zero_kernel<<<(BB*DD + 255)/256, blk>>>();
    {
        dim3 grid(BB, 32);
        vmean_kernel<<<grid, DD>>>();
    }
    {
        size_t total = (size_t)BB * LL * DD;
        broadcast_out_kernel<<<(unsigned)((total + 255)/256), blk>>>(out);
        size_t st = (size_t)BB * u * DD;
        scatter_out_kernel<<<(unsigned)((st + 255)/256), blk>>>(out, u);
    }
}